// round 1
// baseline (speedup 1.0000x reference)
#include <cuda_runtime.h>
#include <cstddef>

#define B_   64
#define C_   768
#define HW_  3136
#define S_   256
#define MT   16384      // B*S rows
#define K1   1536       // 2*C
#define N_   256

// Scratch (allocation-free: __device__ globals)
__device__ float g_feats[(size_t)MT * K1];   // ~100 MB
__device__ float g_h1[(size_t)MT * N_];      // 16 MB
__device__ float g_h2[(size_t)MT * N_];      // 16 MB

// ---------------------------------------------------------------------------
// Gather: feats[row, 0:768] = x[b, :, px], feats[row, 768:1536] = x[b, :, py]
// ---------------------------------------------------------------------------
__global__ void gather_kernel(const float* __restrict__ x,
                              const int* __restrict__ pxs,
                              const int* __restrict__ pys) {
    int row = blockIdx.x;            // 0..16383
    int b   = row >> 8;              // row / 256
    int px0 = pxs[row * 2], px1 = pxs[row * 2 + 1];
    int py0 = pys[row * 2], py1 = pys[row * 2 + 1];
    int ix = px0 * 56 + px1;
    int iy = py0 * 56 + py1;
    const float* xb = x + (size_t)b * C_ * HW_;
    float* fr = g_feats + (size_t)row * K1;
    for (int c = threadIdx.x; c < C_; c += blockDim.x) {
        fr[c]      = __ldg(xb + (size_t)c * HW_ + ix);
        fr[C_ + c] = __ldg(xb + (size_t)c * HW_ + iy);
    }
}

// ---------------------------------------------------------------------------
// deltaxy = float(pxs - pys) + (H-1)
// ---------------------------------------------------------------------------
__global__ void delta_kernel(const int* __restrict__ pxs,
                             const int* __restrict__ pys,
                             float* __restrict__ out) {
    int i = blockIdx.x * blockDim.x + threadIdx.x;
    if (i < MT * 2)
        out[i] = (float)(pxs[i] - pys[i]) + 55.0f;
}

// ---------------------------------------------------------------------------
// Tiled SGEMM: out[M,256] = relu?(A[M,K] @ W[K,256] + bias)
// CTA tile 64x256, thread tile 8x8, BK=16, double-buffered smem,
// register-staged global loads for load/compute overlap.
// ---------------------------------------------------------------------------
__global__ void __launch_bounds__(256, 2)
gemm_bias_relu(const float* __restrict__ A, const float* __restrict__ Wm,
               const float* __restrict__ bias, float* __restrict__ out,
               int K, int do_relu) {
    const int BK = 16;
    __shared__ float As[2][BK][68];    // padded stride 68 to break STS conflicts
    __shared__ float Bs[2][BK][256];

    int tid = threadIdx.x;
    int tx  = tid & 31;        // 0..31  -> column groups
    int ty  = tid >> 5;        // 0..7   -> row groups
    int m0  = blockIdx.x * 64;

    // A-tile loader: 64 rows x 16 k = 256 float4, 1 per thread
    int la_m = tid >> 2;               // 0..63
    int la_k = (tid & 3) << 2;         // 0,4,8,12
    // B-tile loader: 16 k x 256 cols = 1024 float4, 4 per thread (fixed col)
    int kb = tid >> 6;                 // 0..3
    int cB = (tid & 63) << 2;          // 0..252

    const float* Aptr = A  + (size_t)(m0 + la_m) * K + la_k;
    const float* Bptr = Wm + (size_t)kb * N_ + cB;

    float acc[8][8];
    #pragma unroll
    for (int i = 0; i < 8; i++)
        #pragma unroll
        for (int j = 0; j < 8; j++) acc[i][j] = 0.f;

    // preload stage 0
    {
        float4 ra = *(const float4*)Aptr;
        As[0][la_k + 0][la_m] = ra.x;
        As[0][la_k + 1][la_m] = ra.y;
        As[0][la_k + 2][la_m] = ra.z;
        As[0][la_k + 3][la_m] = ra.w;
        #pragma unroll
        for (int j = 0; j < 4; j++) {
            float4 rb = *(const float4*)(Bptr + (size_t)(4 * j) * N_);
            *(float4*)&Bs[0][kb + 4 * j][cB] = rb;
        }
    }
    __syncthreads();

    int nk = K / BK;
    for (int kt = 0; kt < nk; kt++) {
        int cur = kt & 1;
        int nxt = cur ^ 1;
        bool more = (kt + 1 < nk);
        float4 ra;
        float4 rb[4];
        if (more) {
            ra = *(const float4*)(Aptr + (kt + 1) * BK);
            const float* bp = Bptr + (size_t)(kt + 1) * BK * N_;
            #pragma unroll
            for (int j = 0; j < 4; j++)
                rb[j] = *(const float4*)(bp + (size_t)(4 * j) * N_);
        }
        #pragma unroll
        for (int kk = 0; kk < BK; kk++) {
            float4 a0 = *(const float4*)&As[cur][kk][ty * 4];
            float4 a1 = *(const float4*)&As[cur][kk][ty * 4 + 32];
            float4 b0 = *(const float4*)&Bs[cur][kk][tx * 4];
            float4 b1 = *(const float4*)&Bs[cur][kk][tx * 4 + 128];
            float av[8] = {a0.x, a0.y, a0.z, a0.w, a1.x, a1.y, a1.z, a1.w};
            float bv[8] = {b0.x, b0.y, b0.z, b0.w, b1.x, b1.y, b1.z, b1.w};
            #pragma unroll
            for (int i = 0; i < 8; i++)
                #pragma unroll
                for (int j = 0; j < 8; j++)
                    acc[i][j] += av[i] * bv[j];
        }
        if (more) {
            As[nxt][la_k + 0][la_m] = ra.x;
            As[nxt][la_k + 1][la_m] = ra.y;
            As[nxt][la_k + 2][la_m] = ra.z;
            As[nxt][la_k + 3][la_m] = ra.w;
            #pragma unroll
            for (int j = 0; j < 4; j++)
                *(float4*)&Bs[nxt][kb + 4 * j][cB] = rb[j];
        }
        __syncthreads();
    }

    // epilogue: bias + optional relu, coalesced float4 stores
    #pragma unroll
    for (int i = 0; i < 8; i++) {
        int r = m0 + ((i < 4) ? (ty * 4 + i) : (32 + ty * 4 + i - 4));
        #pragma unroll
        for (int jh = 0; jh < 2; jh++) {
            int c = tx * 4 + jh * 128;
            float4 v;
            v.x = acc[i][jh * 4 + 0] + bias[c + 0];
            v.y = acc[i][jh * 4 + 1] + bias[c + 1];
            v.z = acc[i][jh * 4 + 2] + bias[c + 2];
            v.w = acc[i][jh * 4 + 3] + bias[c + 3];
            if (do_relu) {
                v.x = fmaxf(v.x, 0.f);
                v.y = fmaxf(v.y, 0.f);
                v.z = fmaxf(v.z, 0.f);
                v.w = fmaxf(v.w, 0.f);
            }
            *(float4*)&out[(size_t)r * N_ + c] = v;
        }
    }
}

// ---------------------------------------------------------------------------
// GEMM3: pred[row, 0:2] = h2[row,:] @ W3[256,2] + b3 ; one warp per row
// ---------------------------------------------------------------------------
__global__ void gemm3_kernel(const float* __restrict__ h2,
                             const float* __restrict__ W3,
                             const float* __restrict__ b3,
                             float* __restrict__ out) {
    int gwarp = (blockIdx.x * blockDim.x + threadIdx.x) >> 5;
    int lane  = threadIdx.x & 31;
    if (gwarp >= MT) return;
    const float* hr = h2 + (size_t)gwarp * N_;
    float s0 = 0.f, s1 = 0.f;
    #pragma unroll
    for (int k = lane; k < N_; k += 32) {
        float h = hr[k];
        s0 += h * W3[k * 2 + 0];
        s1 += h * W3[k * 2 + 1];
    }
    #pragma unroll
    for (int o = 16; o > 0; o >>= 1) {
        s0 += __shfl_down_sync(0xffffffffu, s0, o);
        s1 += __shfl_down_sync(0xffffffffu, s1, o);
    }
    if (lane == 0) {
        out[gwarp * 2 + 0] = s0 + b3[0];
        out[gwarp * 2 + 1] = s1 + b3[1];
    }
}

// ---------------------------------------------------------------------------
extern "C" void kernel_launch(void* const* d_in, const int* in_sizes, int n_in,
                              void* d_out, int out_size) {
    const float* x  = (const float*)d_in[0];
    const int*   pxs = (const int*)d_in[1];
    const int*   pys = (const int*)d_in[2];
    const float* W1 = (const float*)d_in[3];
    const float* b1 = (const float*)d_in[4];
    const float* W2 = (const float*)d_in[5];
    const float* b2 = (const float*)d_in[6];
    const float* W3 = (const float*)d_in[7];
    const float* b3 = (const float*)d_in[8];
    float* out = (float*)d_out;

    float *feats, *h1, *h2;
    cudaGetSymbolAddress((void**)&feats, g_feats);
    cudaGetSymbolAddress((void**)&h1, g_h1);
    cudaGetSymbolAddress((void**)&h2, g_h2);

    int half = out_size / 2;  // predxy first, deltaxy second

    gather_kernel<<<MT, 256>>>(x, pxs, pys);
    delta_kernel<<<(MT * 2 + 255) / 256, 256>>>(pxs, pys, out + half);
    gemm_bias_relu<<<MT / 64, 256>>>(feats, W1, b1, h1, K1, 1);
    gemm_bias_relu<<<MT / 64, 256>>>(h1, W2, b2, h2, N_, 1);
    gemm3_kernel<<<MT / 8, 256>>>(h2, W3, b3, out);
}

// round 3
// speedup vs baseline: 1.5859x; 1.5859x over previous
#include <cuda_runtime.h>
#include <cuda_bf16.h>
#include <cstdint>
#include <cstddef>

#define MT   16384      // B*S rows
#define K1   1536       // 2*C
#define NN   256
#define C_   768
#define HW_  3136

typedef __nv_bfloat16 bf16;

// ---------------------------------------------------------------------------
// Device scratch (allocation-free)
// ---------------------------------------------------------------------------
static __device__ __align__(128) bf16 g_fhi[(size_t)MT * K1];
static __device__ __align__(128) bf16 g_flo[(size_t)MT * K1];
static __device__ __align__(128) bf16 g_w1hi[(size_t)NN * K1];
static __device__ __align__(128) bf16 g_w1lo[(size_t)NN * K1];
static __device__ __align__(128) bf16 g_w2hi[(size_t)NN * NN];
static __device__ __align__(128) bf16 g_w2lo[(size_t)NN * NN];
static __device__ __align__(128) bf16 g_h1hi[(size_t)MT * NN];   // row-major [m][n]
static __device__ __align__(128) bf16 g_h1lo[(size_t)MT * NN];

// ---------------------------------------------------------------------------
// Helpers
// ---------------------------------------------------------------------------
__device__ __forceinline__ uint32_t s2u(const void* p) {
    uint32_t a;
    asm("{ .reg .u64 t; cvta.to.shared.u64 t, %1; cvt.u32.u64 %0, t; }" : "=r"(a) : "l"(p));
    return a;
}
__device__ __forceinline__ void cpasync16(uint32_t dst, const void* src) {
    asm volatile("cp.async.cg.shared.global [%0], [%1], 16;" :: "r"(dst), "l"(src));
}
__device__ __forceinline__ void cp_commit() { asm volatile("cp.async.commit_group;"); }
template <int N>
__device__ __forceinline__ void cp_wait() { asm volatile("cp.async.wait_group %0;" :: "n"(N)); }

__device__ __forceinline__ void ldsm4(uint32_t& r0, uint32_t& r1, uint32_t& r2, uint32_t& r3,
                                      uint32_t addr) {
    asm volatile("ldmatrix.sync.aligned.m8n8.x4.shared.b16 {%0,%1,%2,%3}, [%4];"
                 : "=r"(r0), "=r"(r1), "=r"(r2), "=r"(r3) : "r"(addr));
}
__device__ __forceinline__ void mma16816(float* c, const uint32_t* a, const uint32_t* b) {
    asm volatile(
        "mma.sync.aligned.m16n8k16.row.col.f32.bf16.bf16.f32 "
        "{%0,%1,%2,%3}, {%4,%5,%6,%7}, {%8,%9}, {%0,%1,%2,%3};"
        : "+f"(c[0]), "+f"(c[1]), "+f"(c[2]), "+f"(c[3])
        : "r"(a[0]), "r"(a[1]), "r"(a[2]), "r"(a[3]), "r"(b[0]), "r"(b[1]));
}
__device__ __forceinline__ uint32_t pack_bf2(float v0, float v1) {
    __nv_bfloat162 t;
    t.x = __float2bfloat16(v0);
    t.y = __float2bfloat16(v1);
    return *(uint32_t*)&t;
}

// ---------------------------------------------------------------------------
// Gather + hi/lo split
// ---------------------------------------------------------------------------
__global__ void gather_split(const float* __restrict__ x,
                             const int* __restrict__ pxs,
                             const int* __restrict__ pys) {
    int row = blockIdx.x;
    int b   = row >> 8;
    int ix = pxs[row * 2] * 56 + pxs[row * 2 + 1];
    int iy = pys[row * 2] * 56 + pys[row * 2 + 1];
    const float* xb = x + (size_t)b * C_ * HW_;
    bf16* fh = g_fhi + (size_t)row * K1;
    bf16* fl = g_flo + (size_t)row * K1;
    for (int c = threadIdx.x; c < C_; c += blockDim.x) {
        float vx = __ldg(xb + (size_t)c * HW_ + ix);
        float vy = __ldg(xb + (size_t)c * HW_ + iy);
        bf16 hx = __float2bfloat16(vx);
        bf16 hy = __float2bfloat16(vy);
        fh[c]      = hx;  fl[c]      = __float2bfloat16(vx - __bfloat162float(hx));
        fh[C_ + c] = hy;  fl[C_ + c] = __float2bfloat16(vy - __bfloat162float(hy));
    }
}

// Weight transpose + split: W[K,256] fp32 -> Wt hi/lo [256][K] bf16
__global__ void wsplit(const float* __restrict__ W, int K,
                       bf16* __restrict__ whi, bf16* __restrict__ wlo) {
    int t = blockIdx.x * blockDim.x + threadIdx.x;
    if (t >= K * NN) return;
    int n = t / K, k = t % K;
    float v = W[(size_t)k * NN + n];
    bf16 h = __float2bfloat16(v);
    whi[(size_t)n * K + k] = h;
    wlo[(size_t)n * K + k] = __float2bfloat16(v - __bfloat162float(h));
}

__global__ void delta_kernel(const int* __restrict__ pxs, const int* __restrict__ pys,
                             float* __restrict__ out) {
    int i = blockIdx.x * blockDim.x + threadIdx.x;
    if (i < MT * 2) out[i] = (float)(pxs[i] - pys[i]) + 55.0f;
}

// ---------------------------------------------------------------------------
// mma.sync GEMM. A[M,K]@Wt[BNtot,K]^T, 3-term bf16 split, fp32 acc.
// Smem rows padded to 144B (BK=64 -> 128B data + 16B) => conflict-free ldmatrix.
// EPI=0: OHi/OLo = split(relu(D+bias)) row-major.
// EPI=1: Out[m,0:2] = relu(D+bias) @ W3 + b3 (full N in one CTA).
// ---------------------------------------------------------------------------
template <int BN, int NWM, int NWN, int WM, int WN, int EPI>
__global__ void __launch_bounds__(NWM * NWN * 32, 1)
gemm_mma(const bf16* __restrict__ Ahi, const bf16* __restrict__ Alo,
         const bf16* __restrict__ Bhi, const bf16* __restrict__ Blo,
         const float* __restrict__ bias, int K,
         bf16* __restrict__ OHi, bf16* __restrict__ OLo,
         const float* __restrict__ W3, const float* __restrict__ b3,
         float* __restrict__ Out) {
    constexpr int BK = 64;
    constexpr int ROWB = 144;               // padded smem row stride (bytes)
    constexpr int AHI = 0;
    constexpr int ALO = 128 * ROWB;
    constexpr int BHI = 2 * 128 * ROWB;
    constexpr int BLO = BHI + BN * ROWB;
    constexpr int STG = BHI + 2 * BN * ROWB;
    constexpr int NTHR = NWM * NWN * 32;
    constexpr int MI = WM / 16;             // m16 frags per warp
    constexpr int NJ = WN / 16;             // n16 (ldmatrix.x4) frags per warp

    extern __shared__ char dsm[];
    __shared__ float red[128][2];

    const int tid  = threadIdx.x;
    const int lane = tid & 31;
    const int wid  = tid >> 5;
    const int wm   = wid / NWN;
    const int wn   = wid % NWN;
    const int m0   = blockIdx.x * 128;
    const int bn0  = blockIdx.y * BN;

    if (EPI == 1 && tid < 256) red[tid >> 1][tid & 1] = 0.0f;

    const uint32_t sbase = s2u(dsm);
    // ldmatrix per-lane offsets
    const int a_row = wm * WM + (lane & 15);
    const int a_kb  = (lane & 16) ? 16 : 0;
    const uint32_t aoff = (uint32_t)(a_row * ROWB + a_kb);
    const int b_row = wn * WN + (lane & 7) + ((lane & 16) ? 8 : 0);
    const int b_kb  = (lane & 8) ? 16 : 0;
    const uint32_t boff = (uint32_t)(BHI + b_row * ROWB + b_kb);

    float acc[MI][2 * NJ][4];
    #pragma unroll
    for (int i = 0; i < MI; i++)
        #pragma unroll
        for (int j = 0; j < 2 * NJ; j++)
            #pragma unroll
            for (int q = 0; q < 4; q++) acc[i][j][q] = 0.0f;

    const int NK = K / BK;

    // ---- stage loader (cp.async) ----
    auto load_stage = [&](int buf, int kt) {
        const uint32_t sd = sbase + buf * STG;
        const int k0 = kt * BK;
        constexpr int CHUNKS = (2 * 128 + 2 * BN) * 8;   // 16B chunks
        #pragma unroll
        for (int c = tid; c < CHUNKS; c += NTHR) {
            int row = c >> 3;
            int kc  = (c & 7);
            int kb  = kc * 16;
            const bf16* src;
            uint32_t dst;
            if (row < 128) {
                src = Ahi + (size_t)(m0 + row) * K + k0 + kc * 8;
                dst = sd + AHI + row * ROWB + kb;
            } else if (row < 256) {
                int r = row - 128;
                src = Alo + (size_t)(m0 + r) * K + k0 + kc * 8;
                dst = sd + ALO + r * ROWB + kb;
            } else if (row < 256 + BN) {
                int r = row - 256;
                src = Bhi + (size_t)(bn0 + r) * K + k0 + kc * 8;
                dst = sd + BHI + r * ROWB + kb;
            } else {
                int r = row - 256 - BN;
                src = Blo + (size_t)(bn0 + r) * K + k0 + kc * 8;
                dst = sd + BLO + r * ROWB + kb;
            }
            cpasync16(dst, src);
        }
        cp_commit();
    };

    load_stage(0, 0);

    for (int kt = 0; kt < NK; kt++) {
        if (kt + 1 < NK) { load_stage((kt + 1) & 1, kt + 1); cp_wait<1>(); }
        else             { cp_wait<0>(); }
        __syncthreads();

        const uint32_t sd = sbase + (kt & 1) * STG;
        #pragma unroll
        for (int kk = 0; kk < BK / 16; kk++) {
            uint32_t ah[MI][4], al[MI][4], bh[NJ][4], bl[NJ][4];
            #pragma unroll
            for (int i = 0; i < MI; i++) {
                uint32_t ad = sd + aoff + i * 16 * ROWB + kk * 32;
                ldsm4(ah[i][0], ah[i][1], ah[i][2], ah[i][3], ad);
                ldsm4(al[i][0], al[i][1], al[i][2], al[i][3], ad + (ALO - AHI));
            }
            #pragma unroll
            for (int j = 0; j < NJ; j++) {
                uint32_t bd = sd + boff + j * 16 * ROWB + kk * 32;
                ldsm4(bh[j][0], bh[j][1], bh[j][2], bh[j][3], bd);
                ldsm4(bl[j][0], bl[j][1], bl[j][2], bl[j][3], bd + (BLO - BHI));
            }
            #pragma unroll
            for (int i = 0; i < MI; i++)
                #pragma unroll
                for (int j = 0; j < NJ; j++) {
                    mma16816(acc[i][2 * j + 0], ah[i], &bh[j][0]);
                    mma16816(acc[i][2 * j + 1], ah[i], &bh[j][2]);
                    mma16816(acc[i][2 * j + 0], ah[i], &bl[j][0]);
                    mma16816(acc[i][2 * j + 1], ah[i], &bl[j][2]);
                    mma16816(acc[i][2 * j + 0], al[i], &bh[j][0]);
                    mma16816(acc[i][2 * j + 1], al[i], &bh[j][2]);
                }
        }
        __syncthreads();
    }

    // ---- epilogue ----
    const int qr = lane >> 2;            // row within frag (0..7)
    const int qc = lane & 3;             // n pair selector
    if (EPI == 0) {
        #pragma unroll
        for (int i = 0; i < MI; i++) {
            #pragma unroll
            for (int j = 0; j < 2 * NJ; j++) {
                int n = bn0 + wn * WN + j * 8 + 2 * qc;
                float bz0 = __ldg(bias + n), bz1 = __ldg(bias + n + 1);
                int mA = m0 + wm * WM + i * 16 + qr;
                float v00 = fmaxf(acc[i][j][0] + bz0, 0.0f);
                float v01 = fmaxf(acc[i][j][1] + bz1, 0.0f);
                float v10 = fmaxf(acc[i][j][2] + bz0, 0.0f);
                float v11 = fmaxf(acc[i][j][3] + bz1, 0.0f);
                uint32_t h0 = pack_bf2(v00, v01);
                uint32_t h1 = pack_bf2(v10, v11);
                *(uint32_t*)&OHi[(size_t)mA * NN + n] = h0;
                *(uint32_t*)&OHi[(size_t)(mA + 8) * NN + n] = h1;
                __nv_bfloat162 hh0 = *(__nv_bfloat162*)&h0;
                __nv_bfloat162 hh1 = *(__nv_bfloat162*)&h1;
                uint32_t l0 = pack_bf2(v00 - __bfloat162float(hh0.x), v01 - __bfloat162float(hh0.y));
                uint32_t l1 = pack_bf2(v10 - __bfloat162float(hh1.x), v11 - __bfloat162float(hh1.y));
                *(uint32_t*)&OLo[(size_t)mA * NN + n] = l0;
                *(uint32_t*)&OLo[(size_t)(mA + 8) * NN + n] = l1;
            }
        }
    } else {
        float s[MI][2][2];
        #pragma unroll
        for (int i = 0; i < MI; i++)
            s[i][0][0] = s[i][0][1] = s[i][1][0] = s[i][1][1] = 0.0f;
        #pragma unroll
        for (int i = 0; i < MI; i++) {
            #pragma unroll
            for (int j = 0; j < 2 * NJ; j++) {
                int n = wn * WN + j * 8 + 2 * qc;
                float bz0 = __ldg(bias + n), bz1 = __ldg(bias + n + 1);
                float w00 = __ldg(W3 + n * 2),     w01 = __ldg(W3 + n * 2 + 1);
                float w10 = __ldg(W3 + n * 2 + 2), w11 = __ldg(W3 + n * 2 + 3);
                float v00 = fmaxf(acc[i][j][0] + bz0, 0.0f);
                float v01 = fmaxf(acc[i][j][1] + bz1, 0.0f);
                float v10 = fmaxf(acc[i][j][2] + bz0, 0.0f);
                float v11 = fmaxf(acc[i][j][3] + bz1, 0.0f);
                s[i][0][0] += v00 * w00 + v01 * w10;
                s[i][0][1] += v00 * w01 + v01 * w11;
                s[i][1][0] += v10 * w00 + v11 * w10;
                s[i][1][1] += v10 * w01 + v11 * w11;
            }
        }
        // quad reduce (lanes sharing same rows differ only in qc)
        #pragma unroll
        for (int i = 0; i < MI; i++)
            #pragma unroll
            for (int r = 0; r < 2; r++)
                #pragma unroll
                for (int o = 0; o < 2; o++) {
                    float v = s[i][r][o];
                    v += __shfl_xor_sync(0xffffffffu, v, 1);
                    v += __shfl_xor_sync(0xffffffffu, v, 2);
                    s[i][r][o] = v;
                }
        if (qc == 0) {
            #pragma unroll
            for (int i = 0; i < MI; i++)
                #pragma unroll
                for (int r = 0; r < 2; r++) {
                    int mrow = wm * WM + i * 16 + r * 8 + qr;
                    atomicAdd(&red[mrow][0], s[i][r][0]);
                    atomicAdd(&red[mrow][1], s[i][r][1]);
                }
        }
        __syncthreads();
        if (tid < 256) {
            int m = tid >> 1, o = tid & 1;
            Out[(size_t)(m0 + m) * 2 + o] = red[m][o] + __ldg(b3 + o);
        }
    }
}

// ---------------------------------------------------------------------------
extern "C" void kernel_launch(void* const* d_in, const int* in_sizes, int n_in,
                              void* d_out, int out_size) {
    const float* x   = (const float*)d_in[0];
    const int*   pxs = (const int*)d_in[1];
    const int*   pys = (const int*)d_in[2];
    const float* W1  = (const float*)d_in[3];
    const float* b1  = (const float*)d_in[4];
    const float* W2  = (const float*)d_in[5];
    const float* b2  = (const float*)d_in[6];
    const float* W3  = (const float*)d_in[7];
    const float* b3  = (const float*)d_in[8];
    float* out = (float*)d_out;

    bf16 *fhi, *flo, *w1hi, *w1lo, *w2hi, *w2lo, *h1hi, *h1lo;
    cudaGetSymbolAddress((void**)&fhi, g_fhi);
    cudaGetSymbolAddress((void**)&flo, g_flo);
    cudaGetSymbolAddress((void**)&w1hi, g_w1hi);
    cudaGetSymbolAddress((void**)&w1lo, g_w1lo);
    cudaGetSymbolAddress((void**)&w2hi, g_w2hi);
    cudaGetSymbolAddress((void**)&w2lo, g_w2lo);
    cudaGetSymbolAddress((void**)&h1hi, g_h1hi);
    cudaGetSymbolAddress((void**)&h1lo, g_h1lo);

    // GEMM1: BN=128, 8 warps (2x4), warp tile 64x32
    auto k1f = gemm_mma<128, 2, 4, 64, 32, 0>;
    // GEMM2: BN=256, 16 warps (4x4), warp tile 32x64, fused GEMM3
    auto k2f = gemm_mma<256, 4, 4, 32, 64, 1>;
    const int SM1 = 2 * ((2 * 128 + 2 * 128) * 144);   // 147456
    const int SM2 = 2 * ((2 * 128 + 2 * 256) * 144);   // 221184
    cudaFuncSetAttribute(k1f, cudaFuncAttributeMaxDynamicSharedMemorySize, SM1);
    cudaFuncSetAttribute(k2f, cudaFuncAttributeMaxDynamicSharedMemorySize, SM2);

    int half = out_size / 2;

    gather_split<<<MT, 256>>>(x, pxs, pys);
    wsplit<<<(K1 * NN) / 256, 256>>>(W1, K1, w1hi, w1lo);
    wsplit<<<(NN * NN) / 256, 256>>>(W2, NN, w2hi, w2lo);
    delta_kernel<<<(MT * 2 + 255) / 256, 256>>>(pxs, pys, out + half);

    k1f<<<dim3(MT / 128, 2), 256, SM1>>>(fhi, flo, w1hi, w1lo, b1, K1,
                                         h1hi, h1lo, nullptr, nullptr, nullptr);
    k2f<<<dim3(MT / 128, 1), 512, SM2>>>(h1hi, h1lo, w2hi, w2lo, b2, NN,
                                         nullptr, nullptr, W3, b3, out);
}

// round 4
// speedup vs baseline: 1.6137x; 1.0175x over previous
#include <cuda_runtime.h>
#include <cuda_bf16.h>
#include <cstdint>
#include <cstddef>

#define MT   16384      // B*S rows
#define K1   1536       // 2*C
#define NN   256
#define C_   768
#define HW_  3136

typedef __nv_bfloat16 bf16;

// ---------------------------------------------------------------------------
// Device scratch (allocation-free)
// ---------------------------------------------------------------------------
static __device__ __align__(128) bf16 g_fhi[(size_t)MT * K1];
static __device__ __align__(128) bf16 g_flo[(size_t)MT * K1];
static __device__ __align__(128) bf16 g_w1hi[(size_t)NN * K1];
static __device__ __align__(128) bf16 g_w1lo[(size_t)NN * K1];
static __device__ __align__(128) bf16 g_w2hi[(size_t)NN * NN];
static __device__ __align__(128) bf16 g_w2lo[(size_t)NN * NN];
static __device__ __align__(128) bf16 g_h1hi[(size_t)MT * NN];   // row-major [m][n]
static __device__ __align__(128) bf16 g_h1lo[(size_t)MT * NN];

// ---------------------------------------------------------------------------
// Helpers
// ---------------------------------------------------------------------------
__device__ __forceinline__ uint32_t s2u(const void* p) {
    uint32_t a;
    asm("{ .reg .u64 t; cvta.to.shared.u64 t, %1; cvt.u32.u64 %0, t; }" : "=r"(a) : "l"(p));
    return a;
}
__device__ __forceinline__ void cpasync16(uint32_t dst, const void* src) {
    asm volatile("cp.async.cg.shared.global [%0], [%1], 16;" :: "r"(dst), "l"(src));
}
__device__ __forceinline__ void cp_commit() { asm volatile("cp.async.commit_group;"); }
template <int N>
__device__ __forceinline__ void cp_wait() { asm volatile("cp.async.wait_group %0;" :: "n"(N)); }

__device__ __forceinline__ void ldsm4(uint32_t& r0, uint32_t& r1, uint32_t& r2, uint32_t& r3,
                                      uint32_t addr) {
    asm volatile("ldmatrix.sync.aligned.m8n8.x4.shared.b16 {%0,%1,%2,%3}, [%4];"
                 : "=r"(r0), "=r"(r1), "=r"(r2), "=r"(r3) : "r"(addr));
}
__device__ __forceinline__ void mma16816(float* c, const uint32_t* a, const uint32_t* b) {
    asm volatile(
        "mma.sync.aligned.m16n8k16.row.col.f32.bf16.bf16.f32 "
        "{%0,%1,%2,%3}, {%4,%5,%6,%7}, {%8,%9}, {%0,%1,%2,%3};"
        : "+f"(c[0]), "+f"(c[1]), "+f"(c[2]), "+f"(c[3])
        : "r"(a[0]), "r"(a[1]), "r"(a[2]), "r"(a[3]), "r"(b[0]), "r"(b[1]));
}
__device__ __forceinline__ uint32_t pack_bf2(float v0, float v1) {
    __nv_bfloat162 t;
    t.x = __float2bfloat16(v0);
    t.y = __float2bfloat16(v1);
    return *(uint32_t*)&t;
}

// ---------------------------------------------------------------------------
// Gather + hi/lo split
// ---------------------------------------------------------------------------
__global__ void gather_split(const float* __restrict__ x,
                             const int* __restrict__ pxs,
                             const int* __restrict__ pys) {
    int row = blockIdx.x;
    int b   = row >> 8;
    int ix = pxs[row * 2] * 56 + pxs[row * 2 + 1];
    int iy = pys[row * 2] * 56 + pys[row * 2 + 1];
    const float* xb = x + (size_t)b * C_ * HW_;
    bf16* fh = g_fhi + (size_t)row * K1;
    bf16* fl = g_flo + (size_t)row * K1;
    for (int c = threadIdx.x; c < C_; c += blockDim.x) {
        float vx = __ldg(xb + (size_t)c * HW_ + ix);
        float vy = __ldg(xb + (size_t)c * HW_ + iy);
        bf16 hx = __float2bfloat16(vx);
        bf16 hy = __float2bfloat16(vy);
        fh[c]      = hx;  fl[c]      = __float2bfloat16(vx - __bfloat162float(hx));
        fh[C_ + c] = hy;  fl[C_ + c] = __float2bfloat16(vy - __bfloat162float(hy));
    }
}

// Weight transpose + split: W[K,256] fp32 -> Wt hi/lo [256][K] bf16
__global__ void wsplit(const float* __restrict__ W, int K,
                       bf16* __restrict__ whi, bf16* __restrict__ wlo) {
    int t = blockIdx.x * blockDim.x + threadIdx.x;
    if (t >= K * NN) return;
    int n = t / K, k = t % K;
    float v = W[(size_t)k * NN + n];
    bf16 h = __float2bfloat16(v);
    whi[(size_t)n * K + k] = h;
    wlo[(size_t)n * K + k] = __float2bfloat16(v - __bfloat162float(h));
}

__global__ void delta_kernel(const int* __restrict__ pxs, const int* __restrict__ pys,
                             float* __restrict__ out) {
    int i = blockIdx.x * blockDim.x + threadIdx.x;
    if (i < MT * 2) out[i] = (float)(pxs[i] - pys[i]) + 55.0f;
}

// ---------------------------------------------------------------------------
// mma.sync GEMM. A[M,K]@Wt[BNtot,K]^T, 3-term bf16 split, fp32 acc.
// Smem rows padded to 144B (BK=64 -> 128B data + 16B) => conflict-free ldmatrix.
// EPI=0: OHi/OLo = split(relu(D+bias)) row-major.
// EPI=1: Out[m,0:2] = relu(D+bias) @ W3 + b3 (full N in one CTA).
// ---------------------------------------------------------------------------
template <int BN, int NWM, int NWN, int WM, int WN, int EPI>
__global__ void __launch_bounds__(NWM * NWN * 32, 1)
gemm_mma(const bf16* __restrict__ Ahi, const bf16* __restrict__ Alo,
         const bf16* __restrict__ Bhi, const bf16* __restrict__ Blo,
         const float* __restrict__ bias, int K,
         bf16* __restrict__ OHi, bf16* __restrict__ OLo,
         const float* __restrict__ W3, const float* __restrict__ b3,
         float* __restrict__ Out) {
    constexpr int BK = 64;
    constexpr int ROWB = 144;               // padded smem row stride (bytes)
    constexpr int AHI = 0;
    constexpr int ALO = 128 * ROWB;
    constexpr int BHI = 2 * 128 * ROWB;
    constexpr int BLO = BHI + BN * ROWB;
    constexpr int STG = BHI + 2 * BN * ROWB;
    constexpr int NTHR = NWM * NWN * 32;
    constexpr int MI = WM / 16;             // m16 frags per warp
    constexpr int NJ = WN / 16;             // n16 (ldmatrix.x4) frags per warp

    extern __shared__ char dsm[];
    __shared__ float red[128][2];

    const int tid  = threadIdx.x;
    const int lane = tid & 31;
    const int wid  = tid >> 5;
    const int wm   = wid / NWN;
    const int wn   = wid % NWN;
    const int m0   = blockIdx.x * 128;
    const int bn0  = blockIdx.y * BN;

    if (EPI == 1 && tid < 256) red[tid >> 1][tid & 1] = 0.0f;

    const uint32_t sbase = s2u(dsm);
    // ldmatrix per-lane offsets
    const int a_row = wm * WM + (lane & 15);
    const int a_kb  = (lane & 16) ? 16 : 0;
    const uint32_t aoff = (uint32_t)(a_row * ROWB + a_kb);
    const int b_row = wn * WN + (lane & 7) + ((lane & 16) ? 8 : 0);
    const int b_kb  = (lane & 8) ? 16 : 0;
    const uint32_t boff = (uint32_t)(BHI + b_row * ROWB + b_kb);

    float acc[MI][2 * NJ][4];
    #pragma unroll
    for (int i = 0; i < MI; i++)
        #pragma unroll
        for (int j = 0; j < 2 * NJ; j++)
            #pragma unroll
            for (int q = 0; q < 4; q++) acc[i][j][q] = 0.0f;

    const int NK = K / BK;

    // ---- stage loader (cp.async) ----
    auto load_stage = [&](int buf, int kt) {
        const uint32_t sd = sbase + buf * STG;
        const int k0 = kt * BK;
        constexpr int CHUNKS = (2 * 128 + 2 * BN) * 8;   // 16B chunks
        #pragma unroll
        for (int c = tid; c < CHUNKS; c += NTHR) {
            int row = c >> 3;
            int kc  = (c & 7);
            int kb  = kc * 16;
            const bf16* src;
            uint32_t dst;
            if (row < 128) {
                src = Ahi + (size_t)(m0 + row) * K + k0 + kc * 8;
                dst = sd + AHI + row * ROWB + kb;
            } else if (row < 256) {
                int r = row - 128;
                src = Alo + (size_t)(m0 + r) * K + k0 + kc * 8;
                dst = sd + ALO + r * ROWB + kb;
            } else if (row < 256 + BN) {
                int r = row - 256;
                src = Bhi + (size_t)(bn0 + r) * K + k0 + kc * 8;
                dst = sd + BHI + r * ROWB + kb;
            } else {
                int r = row - 256 - BN;
                src = Blo + (size_t)(bn0 + r) * K + k0 + kc * 8;
                dst = sd + BLO + r * ROWB + kb;
            }
            cpasync16(dst, src);
        }
        cp_commit();
    };

    load_stage(0, 0);

    for (int kt = 0; kt < NK; kt++) {
        if (kt + 1 < NK) { load_stage((kt + 1) & 1, kt + 1); cp_wait<1>(); }
        else             { cp_wait<0>(); }
        __syncthreads();

        const uint32_t sd = sbase + (kt & 1) * STG;
        #pragma unroll
        for (int kk = 0; kk < BK / 16; kk++) {
            uint32_t ah[MI][4], al[MI][4], bh[NJ][4], bl[NJ][4];
            #pragma unroll
            for (int i = 0; i < MI; i++) {
                uint32_t ad = sd + aoff + i * 16 * ROWB + kk * 32;
                ldsm4(ah[i][0], ah[i][1], ah[i][2], ah[i][3], ad);
                ldsm4(al[i][0], al[i][1], al[i][2], al[i][3], ad + (ALO - AHI));
            }
            #pragma unroll
            for (int j = 0; j < NJ; j++) {
                uint32_t bd = sd + boff + j * 16 * ROWB + kk * 32;
                ldsm4(bh[j][0], bh[j][1], bh[j][2], bh[j][3], bd);
                ldsm4(bl[j][0], bl[j][1], bl[j][2], bl[j][3], bd + (BLO - BHI));
            }
            #pragma unroll
            for (int i = 0; i < MI; i++)
                #pragma unroll
                for (int j = 0; j < NJ; j++) {
                    mma16816(acc[i][2 * j + 0], ah[i], &bh[j][0]);
                    mma16816(acc[i][2 * j + 1], ah[i], &bh[j][2]);
                    mma16816(acc[i][2 * j + 0], ah[i], &bl[j][0]);
                    mma16816(acc[i][2 * j + 1], ah[i], &bl[j][2]);
                    mma16816(acc[i][2 * j + 0], al[i], &bh[j][0]);
                    mma16816(acc[i][2 * j + 1], al[i], &bh[j][2]);
                }
        }
        __syncthreads();
    }

    // ---- epilogue ----
    const int qr = lane >> 2;            // row within frag (0..7)
    const int qc = lane & 3;             // n pair selector
    if (EPI == 0) {
        #pragma unroll
        for (int i = 0; i < MI; i++) {
            #pragma unroll
            for (int j = 0; j < 2 * NJ; j++) {
                int n = bn0 + wn * WN + j * 8 + 2 * qc;
                float bz0 = __ldg(bias + n), bz1 = __ldg(bias + n + 1);
                int mA = m0 + wm * WM + i * 16 + qr;
                float v00 = fmaxf(acc[i][j][0] + bz0, 0.0f);
                float v01 = fmaxf(acc[i][j][1] + bz1, 0.0f);
                float v10 = fmaxf(acc[i][j][2] + bz0, 0.0f);
                float v11 = fmaxf(acc[i][j][3] + bz1, 0.0f);
                uint32_t h0 = pack_bf2(v00, v01);
                uint32_t h1 = pack_bf2(v10, v11);
                *(uint32_t*)&OHi[(size_t)mA * NN + n] = h0;
                *(uint32_t*)&OHi[(size_t)(mA + 8) * NN + n] = h1;
                __nv_bfloat162 hh0 = *(__nv_bfloat162*)&h0;
                __nv_bfloat162 hh1 = *(__nv_bfloat162*)&h1;
                uint32_t l0 = pack_bf2(v00 - __bfloat162float(hh0.x), v01 - __bfloat162float(hh0.y));
                uint32_t l1 = pack_bf2(v10 - __bfloat162float(hh1.x), v11 - __bfloat162float(hh1.y));
                *(uint32_t*)&OLo[(size_t)mA * NN + n] = l0;
                *(uint32_t*)&OLo[(size_t)(mA + 8) * NN + n] = l1;
            }
        }
    } else {
        float s[MI][2][2];
        #pragma unroll
        for (int i = 0; i < MI; i++)
            s[i][0][0] = s[i][0][1] = s[i][1][0] = s[i][1][1] = 0.0f;
        #pragma unroll
        for (int i = 0; i < MI; i++) {
            #pragma unroll
            for (int j = 0; j < 2 * NJ; j++) {
                int n = wn * WN + j * 8 + 2 * qc;
                float bz0 = __ldg(bias + n), bz1 = __ldg(bias + n + 1);
                float w00 = __ldg(W3 + n * 2),     w01 = __ldg(W3 + n * 2 + 1);
                float w10 = __ldg(W3 + n * 2 + 2), w11 = __ldg(W3 + n * 2 + 3);
                float v00 = fmaxf(acc[i][j][0] + bz0, 0.0f);
                float v01 = fmaxf(acc[i][j][1] + bz1, 0.0f);
                float v10 = fmaxf(acc[i][j][2] + bz0, 0.0f);
                float v11 = fmaxf(acc[i][j][3] + bz1, 0.0f);
                s[i][0][0] += v00 * w00 + v01 * w10;
                s[i][0][1] += v00 * w01 + v01 * w11;
                s[i][1][0] += v10 * w00 + v11 * w10;
                s[i][1][1] += v10 * w01 + v11 * w11;
            }
        }
        // quad reduce (lanes sharing same rows differ only in qc)
        #pragma unroll
        for (int i = 0; i < MI; i++)
            #pragma unroll
            for (int r = 0; r < 2; r++)
                #pragma unroll
                for (int o = 0; o < 2; o++) {
                    float v = s[i][r][o];
                    v += __shfl_xor_sync(0xffffffffu, v, 1);
                    v += __shfl_xor_sync(0xffffffffu, v, 2);
                    s[i][r][o] = v;
                }
        if (qc == 0) {
            #pragma unroll
            for (int i = 0; i < MI; i++)
                #pragma unroll
                for (int r = 0; r < 2; r++) {
                    int mrow = wm * WM + i * 16 + r * 8 + qr;
                    atomicAdd(&red[mrow][0], s[i][r][0]);
                    atomicAdd(&red[mrow][1], s[i][r][1]);
                }
        }
        __syncthreads();
        if (tid < 256) {
            int m = tid >> 1, o = tid & 1;
            Out[(size_t)(m0 + m) * 2 + o] = red[m][o] + __ldg(b3 + o);
        }
    }
}

// ---------------------------------------------------------------------------
extern "C" void kernel_launch(void* const* d_in, const int* in_sizes, int n_in,
                              void* d_out, int out_size) {
    const float* x   = (const float*)d_in[0];
    const int*   pxs = (const int*)d_in[1];
    const int*   pys = (const int*)d_in[2];
    const float* W1  = (const float*)d_in[3];
    const float* b1  = (const float*)d_in[4];
    const float* W2  = (const float*)d_in[5];
    const float* b2  = (const float*)d_in[6];
    const float* W3  = (const float*)d_in[7];
    const float* b3  = (const float*)d_in[8];
    float* out = (float*)d_out;

    bf16 *fhi, *flo, *w1hi, *w1lo, *w2hi, *w2lo, *h1hi, *h1lo;
    cudaGetSymbolAddress((void**)&fhi, g_fhi);
    cudaGetSymbolAddress((void**)&flo, g_flo);
    cudaGetSymbolAddress((void**)&w1hi, g_w1hi);
    cudaGetSymbolAddress((void**)&w1lo, g_w1lo);
    cudaGetSymbolAddress((void**)&w2hi, g_w2hi);
    cudaGetSymbolAddress((void**)&w2lo, g_w2lo);
    cudaGetSymbolAddress((void**)&h1hi, g_h1hi);
    cudaGetSymbolAddress((void**)&h1lo, g_h1lo);

    // Both GEMMs: BN=256 (full N per CTA), 16 warps (4x4), warp tile 32x64
    // -> 128 CTAs = exactly one wave on 148 SMs.
    auto k1f = gemm_mma<256, 4, 4, 32, 64, 0>;
    auto k2f = gemm_mma<256, 4, 4, 32, 64, 1>;
    const int SM2 = 2 * ((2 * 128 + 2 * 256) * 144);   // 221184
    cudaFuncSetAttribute(k1f, cudaFuncAttributeMaxDynamicSharedMemorySize, SM2);
    cudaFuncSetAttribute(k2f, cudaFuncAttributeMaxDynamicSharedMemorySize, SM2);

    int half = out_size / 2;

    gather_split<<<MT, 256>>>(x, pxs, pys);
    wsplit<<<(K1 * NN) / 256, 256>>>(W1, K1, w1hi, w1lo);
    wsplit<<<(NN * NN) / 256, 256>>>(W2, NN, w2hi, w2lo);
    k1f<<<dim3(MT / 128, 1), 512, SM2>>>(fhi, flo, w1hi, w1lo, b1, K1,
                                         h1hi, h1lo, nullptr, nullptr, nullptr);
    k2f<<<dim3(MT / 128, 1), 512, SM2>>>(h1hi, h1lo, w2hi, w2lo, b2, NN,
                                         nullptr, nullptr, W3, b3, out);
    delta_kernel<<<(MT * 2 + 255) / 256, 256>>>(pxs, pys, out + half);
}

// round 7
// speedup vs baseline: 1.9261x; 1.1937x over previous
#include <cuda_runtime.h>
#include <cuda_fp16.h>
#include <cstdint>
#include <cstddef>

#define MT   16384      // B*S rows
#define K1   1536       // 2*C
#define NN   256
#define C_   768
#define HW_  3136

// ---------------------------------------------------------------------------
// Device scratch (allocation-free)
// ---------------------------------------------------------------------------
static __device__ __align__(128) __half g_fa[(size_t)MT * K1];     // feats fp16
static __device__ __align__(128) __half g_w1hi[(size_t)NN * K1];
static __device__ __align__(128) __half g_w1lo[(size_t)NN * K1];
static __device__ __align__(128) __half g_w2hi[(size_t)NN * NN];
static __device__ __align__(128) __half g_w2lo[(size_t)NN * NN];
static __device__ __align__(128) __half g_h1[(size_t)MT * NN];     // h1 fp16 row-major

// ---------------------------------------------------------------------------
// Helpers
// ---------------------------------------------------------------------------
__device__ __forceinline__ uint32_t s2u(const void* p) {
    uint32_t a;
    asm("{ .reg .u64 t; cvta.to.shared.u64 t, %1; cvt.u32.u64 %0, t; }" : "=r"(a) : "l"(p));
    return a;
}
__device__ __forceinline__ void cpasync16(uint32_t dst, const void* src) {
    asm volatile("cp.async.cg.shared.global [%0], [%1], 16;" :: "r"(dst), "l"(src));
}
__device__ __forceinline__ void cp_commit() { asm volatile("cp.async.commit_group;"); }
template <int N>
__device__ __forceinline__ void cp_wait() { asm volatile("cp.async.wait_group %0;" :: "n"(N)); }

__device__ __forceinline__ void ldsm4(uint32_t& r0, uint32_t& r1, uint32_t& r2, uint32_t& r3,
                                      uint32_t addr) {
    asm volatile("ldmatrix.sync.aligned.m8n8.x4.shared.b16 {%0,%1,%2,%3}, [%4];"
                 : "=r"(r0), "=r"(r1), "=r"(r2), "=r"(r3) : "r"(addr));
}
__device__ __forceinline__ void mma16816(float* c, const uint32_t* a, const uint32_t* b) {
    asm volatile(
        "mma.sync.aligned.m16n8k16.row.col.f32.f16.f16.f32 "
        "{%0,%1,%2,%3}, {%4,%5,%6,%7}, {%8,%9}, {%0,%1,%2,%3};"
        : "+f"(c[0]), "+f"(c[1]), "+f"(c[2]), "+f"(c[3])
        : "r"(a[0]), "r"(a[1]), "r"(a[2]), "r"(a[3]), "r"(b[0]), "r"(b[1]));
}
__device__ __forceinline__ uint32_t pack_h2(float v0, float v1) {
    __half2 t = __floats2half2_rn(v0, v1);
    return *(uint32_t*)&t;
}

// ---------------------------------------------------------------------------
// Gather -> fp16 feats
// ---------------------------------------------------------------------------
__global__ void gather_fp16(const float* __restrict__ x,
                            const int* __restrict__ pxs,
                            const int* __restrict__ pys) {
    int row = blockIdx.x;
    int b   = row >> 8;
    int ix = pxs[row * 2] * 56 + pxs[row * 2 + 1];
    int iy = pys[row * 2] * 56 + pys[row * 2 + 1];
    const float* xb = x + (size_t)b * C_ * HW_;
    __half* fr = g_fa + (size_t)row * K1;
    for (int c = threadIdx.x; c < C_; c += blockDim.x) {
        float vx = __ldg(xb + (size_t)c * HW_ + ix);
        float vy = __ldg(xb + (size_t)c * HW_ + iy);
        fr[c]      = __float2half(vx);
        fr[C_ + c] = __float2half(vy);
    }
}

// Weight transpose + split: W[K,256] fp32 -> Wt hi/lo [256][K] fp16
__global__ void wsplit(const float* __restrict__ W, int K,
                       __half* __restrict__ whi, __half* __restrict__ wlo) {
    int t = blockIdx.x * blockDim.x + threadIdx.x;
    if (t >= K * NN) return;
    int n = t / K, k = t % K;
    float v = W[(size_t)k * NN + n];
    __half h = __float2half(v);
    whi[(size_t)n * K + k] = h;
    wlo[(size_t)n * K + k] = __float2half(v - __half2float(h));
}

__global__ void delta_kernel(const int* __restrict__ pxs, const int* __restrict__ pys,
                             float* __restrict__ out) {
    int i = blockIdx.x * blockDim.x + threadIdx.x;
    if (i < MT * 2) out[i] = (float)(pxs[i] - pys[i]) + 55.0f;
}

// ---------------------------------------------------------------------------
// mma.sync GEMM. A[M,K](fp16) @ Wt[BN,K]^T (fp16 hi+lo), fp32 acc, 2 terms.
// Smem rows padded to 144B (BK=64 -> 128B data + 16B) => conflict-free ldmatrix.
// EPI=0: O = fp16(relu(D+bias)) row-major.
// EPI=1: Out[m,0:2] = relu(D+bias) @ W3 + b3 (full N in one CTA).
// ---------------------------------------------------------------------------
template <int BN, int NWM, int NWN, int WM, int WN, int EPI>
__global__ void __launch_bounds__(NWM * NWN * 32, 1)
gemm_mma(const __half* __restrict__ A,
         const __half* __restrict__ Bhi, const __half* __restrict__ Blo,
         const float* __restrict__ bias, int K,
         __half* __restrict__ O,
         const float* __restrict__ W3, const float* __restrict__ b3,
         float* __restrict__ Out) {
    constexpr int BK = 64;
    constexpr int ROWB = 144;               // padded smem row stride (bytes)
    constexpr int ABASE = 0;
    constexpr int BHI = 128 * ROWB;
    constexpr int BLO = BHI + BN * ROWB;
    constexpr int STG = BHI + 2 * BN * ROWB;
    constexpr int NTHR = NWM * NWN * 32;
    constexpr int MI = WM / 16;             // m16 frags per warp
    constexpr int NJ = WN / 16;             // n16 (ldmatrix.x4) frags per warp

    extern __shared__ char dsm[];
    __shared__ float red[128][2];

    const int tid  = threadIdx.x;
    const int lane = tid & 31;
    const int wid  = tid >> 5;
    const int wm   = wid / NWN;
    const int wn   = wid % NWN;
    const int m0   = blockIdx.x * 128;

    if (EPI == 1 && tid < 256) red[tid >> 1][tid & 1] = 0.0f;

    const uint32_t sbase = s2u(dsm);
    // ldmatrix per-lane offsets
    const int a_row = wm * WM + (lane & 15);
    const int a_kb  = (lane & 16) ? 16 : 0;
    const uint32_t aoff = (uint32_t)(ABASE + a_row * ROWB + a_kb);
    const int b_row = wn * WN + (lane & 7) + ((lane & 16) ? 8 : 0);
    const int b_kb  = (lane & 8) ? 16 : 0;
    const uint32_t boff = (uint32_t)(BHI + b_row * ROWB + b_kb);

    float acc[MI][2 * NJ][4];
    #pragma unroll
    for (int i = 0; i < MI; i++)
        #pragma unroll
        for (int j = 0; j < 2 * NJ; j++)
            #pragma unroll
            for (int q = 0; q < 4; q++) acc[i][j][q] = 0.0f;

    const int NK = K / BK;

    // ---- stage loader (cp.async): A 128 rows, Bhi BN rows, Blo BN rows ----
    auto load_stage = [&](int buf, int kt) {
        const uint32_t sd = sbase + buf * STG;
        const int k0 = kt * BK;
        constexpr int CHUNKS = (128 + 2 * BN) * 8;   // 16B chunks
        #pragma unroll
        for (int c = tid; c < CHUNKS; c += NTHR) {
            int row = c >> 3;
            int kc  = (c & 7);
            int kb  = kc * 16;
            const __half* src;
            uint32_t dst;
            if (row < 128) {
                src = A + (size_t)(m0 + row) * K + k0 + kc * 8;
                dst = sd + ABASE + row * ROWB + kb;
            } else if (row < 128 + BN) {
                int r = row - 128;
                src = Bhi + (size_t)r * K + k0 + kc * 8;
                dst = sd + BHI + r * ROWB + kb;
            } else {
                int r = row - 128 - BN;
                src = Blo + (size_t)r * K + k0 + kc * 8;
                dst = sd + BLO + r * ROWB + kb;
            }
            cpasync16(dst, src);
        }
        cp_commit();
    };

    load_stage(0, 0);

    for (int kt = 0; kt < NK; kt++) {
        if (kt + 1 < NK) { load_stage((kt + 1) & 1, kt + 1); cp_wait<1>(); }
        else             { cp_wait<0>(); }
        __syncthreads();

        const uint32_t sd = sbase + (kt & 1) * STG;
        #pragma unroll
        for (int kk = 0; kk < BK / 16; kk++) {
            uint32_t a[MI][4], bh[NJ][4], bl[NJ][4];
            #pragma unroll
            for (int i = 0; i < MI; i++) {
                uint32_t ad = sd + aoff + i * 16 * ROWB + kk * 32;
                ldsm4(a[i][0], a[i][1], a[i][2], a[i][3], ad);
            }
            #pragma unroll
            for (int j = 0; j < NJ; j++) {
                uint32_t bd = sd + boff + j * 16 * ROWB + kk * 32;
                ldsm4(bh[j][0], bh[j][1], bh[j][2], bh[j][3], bd);
                ldsm4(bl[j][0], bl[j][1], bl[j][2], bl[j][3], bd + (BLO - BHI));
            }
            #pragma unroll
            for (int i = 0; i < MI; i++)
                #pragma unroll
                for (int j = 0; j < NJ; j++) {
                    mma16816(acc[i][2 * j + 0], a[i], &bh[j][0]);
                    mma16816(acc[i][2 * j + 1], a[i], &bh[j][2]);
                    mma16816(acc[i][2 * j + 0], a[i], &bl[j][0]);
                    mma16816(acc[i][2 * j + 1], a[i], &bl[j][2]);
                }
        }
        __syncthreads();
    }

    // ---- epilogue ----
    const int qr = lane >> 2;            // row within frag (0..7)
    const int qc = lane & 3;             // n pair selector
    if (EPI == 0) {
        #pragma unroll
        for (int i = 0; i < MI; i++) {
            #pragma unroll
            for (int j = 0; j < 2 * NJ; j++) {
                int n = wn * WN + j * 8 + 2 * qc;
                float bz0 = __ldg(bias + n), bz1 = __ldg(bias + n + 1);
                int mA = m0 + wm * WM + i * 16 + qr;
                float v00 = fmaxf(acc[i][j][0] + bz0, 0.0f);
                float v01 = fmaxf(acc[i][j][1] + bz1, 0.0f);
                float v10 = fmaxf(acc[i][j][2] + bz0, 0.0f);
                float v11 = fmaxf(acc[i][j][3] + bz1, 0.0f);
                *(uint32_t*)&O[(size_t)mA * NN + n]       = pack_h2(v00, v01);
                *(uint32_t*)&O[(size_t)(mA + 8) * NN + n] = pack_h2(v10, v11);
            }
        }
    } else {
        float s[MI][2][2];
        #pragma unroll
        for (int i = 0; i < MI; i++)
            s[i][0][0] = s[i][0][1] = s[i][1][0] = s[i][1][1] = 0.0f;
        #pragma unroll
        for (int i = 0; i < MI; i++) {
            #pragma unroll
            for (int j = 0; j < 2 * NJ; j++) {
                int n = wn * WN + j * 8 + 2 * qc;
                float bz0 = __ldg(bias + n), bz1 = __ldg(bias + n + 1);
                float w00 = __ldg(W3 + n * 2),     w01 = __ldg(W3 + n * 2 + 1);
                float w10 = __ldg(W3 + n * 2 + 2), w11 = __ldg(W3 + n * 2 + 3);
                float v00 = fmaxf(acc[i][j][0] + bz0, 0.0f);
                float v01 = fmaxf(acc[i][j][1] + bz1, 0.0f);
                float v10 = fmaxf(acc[i][j][2] + bz0, 0.0f);
                float v11 = fmaxf(acc[i][j][3] + bz1, 0.0f);
                s[i][0][0] += v00 * w00 + v01 * w10;
                s[i][0][1] += v00 * w01 + v01 * w11;
                s[i][1][0] += v10 * w00 + v11 * w10;
                s[i][1][1] += v10 * w01 + v11 * w11;
            }
        }
        // quad reduce (lanes sharing same rows differ only in qc)
        #pragma unroll
        for (int i = 0; i < MI; i++)
            #pragma unroll
            for (int r = 0; r < 2; r++)
                #pragma unroll
                for (int o = 0; o < 2; o++) {
                    float v = s[i][r][o];
                    v += __shfl_xor_sync(0xffffffffu, v, 1);
                    v += __shfl_xor_sync(0xffffffffu, v, 2);
                    s[i][r][o] = v;
                }
        if (qc == 0) {
            #pragma unroll
            for (int i = 0; i < MI; i++)
                #pragma unroll
                for (int r = 0; r < 2; r++) {
                    int mrow = wm * WM + i * 16 + r * 8 + qr;
                    atomicAdd(&red[mrow][0], s[i][r][0]);
                    atomicAdd(&red[mrow][1], s[i][r][1]);
                }
        }
        __syncthreads();
        if (tid < 256) {
            int m = tid >> 1, o = tid & 1;
            Out[(size_t)(m0 + m) * 2 + o] = red[m][o] + __ldg(b3 + o);
        }
    }
}

// ---------------------------------------------------------------------------
extern "C" void kernel_launch(void* const* d_in, const int* in_sizes, int n_in,
                              void* d_out, int out_size) {
    const float* x   = (const float*)d_in[0];
    const int*   pxs = (const int*)d_in[1];
    const int*   pys = (const int*)d_in[2];
    const float* W1  = (const float*)d_in[3];
    const float* b1  = (const float*)d_in[4];
    const float* W2  = (const float*)d_in[5];
    const float* b2  = (const float*)d_in[6];
    const float* W3  = (const float*)d_in[7];
    const float* b3  = (const float*)d_in[8];
    float* out = (float*)d_out;

    __half *fa, *w1hi, *w1lo, *w2hi, *w2lo, *h1;
    cudaGetSymbolAddress((void**)&fa, g_fa);
    cudaGetSymbolAddress((void**)&w1hi, g_w1hi);
    cudaGetSymbolAddress((void**)&w1lo, g_w1lo);
    cudaGetSymbolAddress((void**)&w2hi, g_w2hi);
    cudaGetSymbolAddress((void**)&w2lo, g_w2lo);
    cudaGetSymbolAddress((void**)&h1, g_h1);

    // Both GEMMs: BN=256 (full N per CTA), 16 warps (4x4), warp tile 32x64
    auto k1f = gemm_mma<256, 4, 4, 32, 64, 0>;
    auto k2f = gemm_mma<256, 4, 4, 32, 64, 1>;
    const int SM = 2 * ((128 + 2 * 256) * 144);   // 184320
    cudaFuncSetAttribute(k1f, cudaFuncAttributeMaxDynamicSharedMemorySize, SM);
    cudaFuncSetAttribute(k2f, cudaFuncAttributeMaxDynamicSharedMemorySize, SM);

    int half = out_size / 2;

    gather_fp16<<<MT, 256>>>(x, pxs, pys);
    wsplit<<<(K1 * NN) / 256, 256>>>(W1, K1, w1hi, w1lo);
    wsplit<<<(NN * NN) / 256, 256>>>(W2, NN, w2hi, w2lo);
    // signature: (A, Bhi, Blo, bias, K, O, W3, b3, Out) — 9 args, dummies cast.
    k1f<<<dim3(MT / 128, 1), 512, SM>>>(fa, w1hi, w1lo, b1, K1,
                                        h1,
                                        (const float*)nullptr,
                                        (const float*)nullptr,
                                        (float*)nullptr);
    k2f<<<dim3(MT / 128, 1), 512, SM>>>(h1, w2hi, w2lo, b2, NN,
                                        (__half*)nullptr,
                                        W3, b3, out);
    delta_kernel<<<(MT * 2 + 255) / 256, 256>>>(pxs, pys, out + half);
}